// round 7
// baseline (speedup 1.0000x reference)
#include <cuda_runtime.h>
#include <cstdint>

#define NN 100000
#define EE 600000
#define DD 128
#define GB 98            // k_graph grid (all blocks resident: 98 <= 148 SMs)
#define GT 1024          // k_graph block

// ---- device scratch (allocation-free rule: __device__ globals) ----
__device__ __align__(16) float g_h1w[(size_t)NN * DD];   // x @ W1
__device__ __align__(16) float2 g_h2w[NN];               // relu(agg1+b1) @ W2
__device__ __align__(16) uint32_t g_wh[DD * DD];         // tf32 hi split of W1
__device__ __align__(16) uint32_t g_wl[DD * DD];         // tf32 lo split of W1
__device__ int   g_cnt[NN];      // zeroed at end of each pass (phase2)
__device__ int   g_cur[NN];      // zeroed by k_agg1 each pass
__device__ int   g_off[NN + 1];
__device__ int   g_bsum[GB];
__device__ int   g_csr[EE];
__device__ float g_dinv[NN];
__device__ int   g_ctr[3];       // grid barriers; zeroed by k_agg1 each pass

// ---------------- tf32 helpers ----------------
__device__ __forceinline__ uint32_t f2tf(float f) {
    uint32_t u;
    asm("cvt.rna.tf32.f32 %0, %1;" : "=r"(u) : "f"(f));
    return u;
}

__device__ __forceinline__ void mma8(float* c, const uint32_t* a, const uint32_t* b) {
    asm volatile(
        "mma.sync.aligned.m16n8k8.row.col.f32.tf32.tf32.f32 "
        "{%0,%1,%2,%3},{%4,%5,%6,%7},{%8,%9},{%0,%1,%2,%3};"
        : "+f"(c[0]), "+f"(c[1]), "+f"(c[2]), "+f"(c[3])
        : "r"(a[0]), "r"(a[1]), "r"(a[2]), "r"(a[3]), "r"(b[0]), "r"(b[1]));
}

// ---------------- grid barrier (all GB blocks resident) ----------------
__device__ __forceinline__ void gsync(int idx, int nb) {
    __syncthreads();
    if (threadIdx.x == 0) {
        __threadfence();                       // release
        atomicAdd(&g_ctr[idx], 1);
        while (((volatile int*)g_ctr)[idx] < nb) { }
        __threadfence();                       // acquire
    }
    __syncthreads();
}

// ============ k_graph: detect + count + wsplit + scan + dinv + fill ============
__global__ void __launch_bounds__(GT) k_graph(const void* __restrict__ ei,
                                              const float* __restrict__ W1,
                                              int n, int e, int nb) {
    __shared__ int s_is64;
    __shared__ int wsum[32];
    __shared__ int s_pre;
    int tid = threadIdx.x, lane = tid & 31, wid = tid >> 5;
    int b = blockIdx.x;
    int gstep = nb * GT;
    int gtid = b * GT + tid;

    // per-block edge dtype detect: int64 edges have all odd 32-bit words == 0
    if (tid == 0) {
        const unsigned* w = (const unsigned*)ei;
        int all0 = 1;
        for (int j = 1; j < 128; j += 2) all0 &= (w[j] == 0u);
        s_is64 = all0;
    }
    __syncthreads();
    int is64 = s_is64;

    // ---- phase0: degree count + W1 tf32 split ----
    for (int i = gtid; i < e; i += gstep) {
        int t = is64 ? (int)((const long long*)ei)[(long long)e + i]
                     : ((const int*)ei)[e + i];
        if ((unsigned)t < (unsigned)n) atomicAdd(&g_cnt[t], 1);
    }
    for (int i = gtid; i < DD * DD; i += gstep) {
        float f = W1[i];
        uint32_t h = f2tf(f);
        g_wh[i] = h;
        g_wl[i] = f2tf(f - __uint_as_float(h));
    }
    gsync(0, nb);

    // ---- phase1: per-block exclusive scan of its 1024-count segment ----
    int i = b * GT + tid;
    int v = (i < n) ? g_cnt[i] : 0;
    int incl = v;
#pragma unroll
    for (int d = 1; d < 32; d <<= 1) {
        int y = __shfl_up_sync(0xffffffffu, incl, d);
        if (lane >= d) incl += y;
    }
    if (lane == 31) wsum[wid] = incl;
    __syncthreads();
    if (wid == 0) {
        int s = wsum[lane];
#pragma unroll
        for (int d = 1; d < 32; d <<= 1) {
            int y = __shfl_up_sync(0xffffffffu, s, d);
            if (lane >= d) s += y;
        }
        wsum[lane] = s;
    }
    __syncthreads();
    int wprev = wid ? wsum[wid - 1] : 0;
    int excl = wprev + incl - v;
    if (i < n) g_off[i] = excl;
    if (tid == GT - 1) g_bsum[b] = wprev + incl;
    gsync(1, nb);

    // ---- phase2: propagate block prefix; dinv; zero g_cnt for next replay ----
    if (tid == 0) {
        int p = 0;
        for (int j = 0; j < b; j++) p += g_bsum[j];
        s_pre = p;
        if (b == nb - 1) g_off[n] = p + g_bsum[b];
    }
    __syncthreads();
    if (i < n) {
        g_off[i] += s_pre;
        g_dinv[i] = rsqrtf((float)(g_cnt[i] + 1));   // +1 = self-loop
        g_cnt[i] = 0;
    }
    gsync(2, nb);

    // ---- phase3: CSR fill ----
    for (int idx = gtid; idx < e; idx += gstep) {
        int t = is64 ? (int)((const long long*)ei)[(long long)e + idx]
                     : ((const int*)ei)[e + idx];
        int s = is64 ? (int)((const long long*)ei)[idx]
                     : ((const int*)ei)[idx];
        if ((unsigned)t < (unsigned)n && (unsigned)s < (unsigned)n) {
            int p = atomicAdd(&g_cur[t], 1);
            g_csr[g_off[t] + p] = s;
        }
    }
}

#define SX 136   // smem row stride in words (conflict-free fragment loads)

// ---------------- GEMM1: 3xtf32, double-buffered ----------------
__global__ void __launch_bounds__(256, 2)
k_gemm1_tc(const float* __restrict__ x, int n) {
    __shared__ uint32_t Xh[2][16 * SX], Xl[2][16 * SX];
    __shared__ uint32_t Wh[2][16 * SX], Wl[2][16 * SX];
    int tid = threadIdx.x;
    int wid = tid >> 5, lane = tid & 31;
    int gid = lane >> 2, tig = lane & 3;
    int warpM = wid & 3;
    int warpN = wid >> 2;
    int row0 = blockIdx.x * 128;

    float acc[2][8][4];
#pragma unroll
    for (int mt = 0; mt < 2; mt++)
#pragma unroll
        for (int nt = 0; nt < 8; nt++)
#pragma unroll
            for (int j = 0; j < 4; j++) acc[mt][nt][j] = 0.f;

    auto load_chunk = [&](int kc, int b) {
        int kk = kc * 16;
#pragma unroll
        for (int j = 0; j < 2; j++) {
            int idx = tid + j * 256;
            int r = idx >> 2, kq = idx & 3;
            float4 v = make_float4(0.f, 0.f, 0.f, 0.f);
            if (row0 + r < n)
                v = *(const float4*)(x + (size_t)(row0 + r) * DD + kk + kq * 4);
            float f[4] = {v.x, v.y, v.z, v.w};
#pragma unroll
            for (int i = 0; i < 4; i++) {
                uint32_t h = f2tf(f[i]);
                Xh[b][(kq * 4 + i) * SX + r] = h;
                Xl[b][(kq * 4 + i) * SX + r] = f2tf(f[i] - __uint_as_float(h));
            }
        }
#pragma unroll
        for (int j = 0; j < 2; j++) {
            int idx = tid + j * 256;
            int k = idx >> 5, c4 = idx & 31;
            *(uint4*)&Wh[b][k * SX + c4 * 4] =
                ((const uint4*)g_wh)[(size_t)(kk + k) * 32 + c4];
            *(uint4*)&Wl[b][k * SX + c4 * 4] =
                ((const uint4*)g_wl)[(size_t)(kk + k) * 32 + c4];
        }
    };

    load_chunk(0, 0);
    __syncthreads();

    for (int kc = 0; kc < 8; kc++) {
        int cur = kc & 1;
        if (kc < 7) load_chunk(kc + 1, cur ^ 1);
#pragma unroll
        for (int kb = 0; kb < 16; kb += 8) {
            uint32_t ah[2][4], al[2][4];
#pragma unroll
            for (int mt = 0; mt < 2; mt++) {
                int r = warpM * 32 + mt * 16 + gid;
                int kr0 = (kb + tig) * SX, kr4 = (kb + tig + 4) * SX;
                ah[mt][0] = Xh[cur][kr0 + r];     al[mt][0] = Xl[cur][kr0 + r];
                ah[mt][1] = Xh[cur][kr0 + r + 8]; al[mt][1] = Xl[cur][kr0 + r + 8];
                ah[mt][2] = Xh[cur][kr4 + r];     al[mt][2] = Xl[cur][kr4 + r];
                ah[mt][3] = Xh[cur][kr4 + r + 8]; al[mt][3] = Xl[cur][kr4 + r + 8];
            }
#pragma unroll
            for (int nt = 0; nt < 8; nt++) {
                int c = warpN * 64 + nt * 8 + gid;
                uint32_t bh[2], bl[2];
                bh[0] = Wh[cur][(kb + tig) * SX + c];
                bh[1] = Wh[cur][(kb + tig + 4) * SX + c];
                bl[0] = Wl[cur][(kb + tig) * SX + c];
                bl[1] = Wl[cur][(kb + tig + 4) * SX + c];
#pragma unroll
                for (int mt = 0; mt < 2; mt++) {
                    mma8(acc[mt][nt], ah[mt], bh);
                    mma8(acc[mt][nt], al[mt], bh);
                    mma8(acc[mt][nt], ah[mt], bl);
                }
            }
        }
        __syncthreads();
    }

#pragma unroll
    for (int mt = 0; mt < 2; mt++) {
#pragma unroll
        for (int nt = 0; nt < 8; nt++) {
            int row = row0 + warpM * 32 + mt * 16 + gid;
            int col = warpN * 64 + nt * 8 + 2 * tig;
            if (row < n)
                *(float2*)&g_h1w[(size_t)row * DD + col] =
                    make_float2(acc[mt][nt][0], acc[mt][nt][1]);
            if (row + 8 < n)
                *(float2*)&g_h1w[(size_t)(row + 8) * DD + col] =
                    make_float2(acc[mt][nt][2], acc[mt][nt][3]);
        }
    }
}

// ------- agg1 + bias + relu + W2 projection; also resets g_cur/g_ctr -------
__global__ void __launch_bounds__(256) k_agg1(const float* __restrict__ b1,
                                              const float* __restrict__ W2, int n) {
    int gw = (blockIdx.x * blockDim.x + threadIdx.x) >> 5;
    int lane = threadIdx.x & 31;
    if (gw >= n) return;
    if (lane == 0) {
        g_cur[gw] = 0;                       // reset for next replay
        if (gw == 0) { g_ctr[0] = 0; g_ctr[1] = 0; g_ctr[2] = 0; }
    }
    float dn = g_dinv[gw];
    const float4* h = (const float4*)g_h1w;
    float4 own = h[(size_t)gw * 32 + lane];
    float s = dn * dn;
    float a0x = own.x * s, a0y = own.y * s, a0z = own.z * s, a0w = own.w * s;
    float a1x = 0.f, a1y = 0.f, a1z = 0.f, a1w = 0.f;
    int e0 = g_off[gw], e1 = g_off[gw + 1];
    int e = e0;
    for (; e + 1 < e1; e += 2) {
        int s0 = g_csr[e], s1 = g_csr[e + 1];
        float w0 = g_dinv[s0] * dn, w1 = g_dinv[s1] * dn;
        float4 v0 = h[(size_t)s0 * 32 + lane];
        float4 v1 = h[(size_t)s1 * 32 + lane];
        a0x += v0.x * w0; a0y += v0.y * w0; a0z += v0.z * w0; a0w += v0.w * w0;
        a1x += v1.x * w1; a1y += v1.y * w1; a1z += v1.z * w1; a1w += v1.w * w1;
    }
    if (e < e1) {
        int s0 = g_csr[e];
        float w0 = g_dinv[s0] * dn;
        float4 v0 = h[(size_t)s0 * 32 + lane];
        a0x += v0.x * w0; a0y += v0.y * w0; a0z += v0.z * w0; a0w += v0.w * w0;
    }
    float4 b = ((const float4*)b1)[lane];
    float ax = fmaxf(a0x + a1x + b.x, 0.f);
    float ay = fmaxf(a0y + a1y + b.y, 0.f);
    float az = fmaxf(a0z + a1z + b.z, 0.f);
    float aw = fmaxf(a0w + a1w + b.w, 0.f);
    const float2* w2 = (const float2*)W2;
    float2 w0 = w2[lane * 4 + 0], w1 = w2[lane * 4 + 1];
    float2 w2v = w2[lane * 4 + 2], w3 = w2[lane * 4 + 3];
    float o0 = ax * w0.x + ay * w1.x + az * w2v.x + aw * w3.x;
    float o1 = ax * w0.y + ay * w1.y + az * w2v.y + aw * w3.y;
#pragma unroll
    for (int d = 16; d; d >>= 1) {
        o0 += __shfl_xor_sync(0xffffffffu, o0, d);
        o1 += __shfl_xor_sync(0xffffffffu, o1, d);
    }
    if (lane == 0) g_h2w[gw] = make_float2(o0, o1);
}

// ---------------- Aggregate layer 2 (thread per node) ----------------
__global__ void k_agg2(const float* __restrict__ b2, float* __restrict__ out, int n) {
    int i = blockIdx.x * blockDim.x + threadIdx.x;
    if (i >= n) return;
    float dn = g_dinv[i];
    float2 hv = g_h2w[i];
    float o0 = hv.x * dn * dn + b2[0];
    float o1 = hv.y * dn * dn + b2[1];
    int e0 = g_off[i], e1 = g_off[i + 1];
    for (int e = e0; e < e1; e++) {
        int src = g_csr[e];
        float w = g_dinv[src] * dn;
        float2 v = g_h2w[src];
        o0 += v.x * w;
        o1 += v.y * w;
    }
    ((float2*)out)[i] = make_float2(o0, o1);
}

// ---------------- launch ----------------
extern "C" void kernel_launch(void* const* d_in, const int* in_sizes, int n_in,
                              void* d_out, int out_size) {
    const float* x  = (const float*)d_in[0];
    const void*  ei = d_in[1];
    const float* W1 = (const float*)d_in[2];
    const float* b1 = (const float*)d_in[3];
    const float* W2 = (const float*)d_in[4];
    const float* b2 = (const float*)d_in[5];
    float* out = (float*)d_out;

    const int n = in_sizes[0] / DD;       // 100000
    const int e = in_sizes[1] / 2;        // 600000

    k_graph<<<GB, GT>>>(ei, W1, n, e, GB);
    k_gemm1_tc<<<(n + 127) / 128, 256>>>(x, n);
    k_agg1<<<(n + 7) / 8, 256>>>(b1, W2, n);
    k_agg2<<<(n + 255) / 256, 256>>>(b2, out, n);
}

// round 8
// speedup vs baseline: 1.0496x; 1.0496x over previous
#include <cuda_runtime.h>
#include <cuda_fp16.h>
#include <cstdint>

#define NN 100000
#define EE 600000
#define DD 128
#define GB 98            // k_graph grid (all blocks resident: 98 <= 148 SMs)
#define GT 1024          // k_graph block

// ---- device scratch (allocation-free rule: __device__ globals) ----
__device__ __align__(16) uint32_t g_h1h[(size_t)NN * 64]; // x @ W1, fp16x2 packed
__device__ __align__(16) float2 g_h2w[NN];               // relu(agg1+b1) @ W2
__device__ __align__(16) uint32_t g_wh[DD * DD];         // tf32 hi split of W1
__device__ __align__(16) uint32_t g_wl[DD * DD];         // tf32 lo split of W1
__device__ int   g_cnt[NN];      // zeroed at end of each pass (phase2)
__device__ int   g_cur[NN];      // zeroed by k_agg1 each pass
__device__ int   g_off[NN + 1];
__device__ int   g_bsum[GB];
__device__ int   g_csr[EE];
__device__ float g_dinv[NN];
__device__ int   g_ctr[3];       // grid barriers; zeroed by k_agg1 each pass

// ---------------- tf32 helpers ----------------
__device__ __forceinline__ uint32_t f2tf(float f) {
    uint32_t u;
    asm("cvt.rna.tf32.f32 %0, %1;" : "=r"(u) : "f"(f));
    return u;
}

__device__ __forceinline__ void mma8(float* c, const uint32_t* a, const uint32_t* b) {
    asm volatile(
        "mma.sync.aligned.m16n8k8.row.col.f32.tf32.tf32.f32 "
        "{%0,%1,%2,%3},{%4,%5,%6,%7},{%8,%9},{%0,%1,%2,%3};"
        : "+f"(c[0]), "+f"(c[1]), "+f"(c[2]), "+f"(c[3])
        : "r"(a[0]), "r"(a[1]), "r"(a[2]), "r"(a[3]), "r"(b[0]), "r"(b[1]));
}

// ---------------- grid barrier (all GB blocks resident) ----------------
__device__ __forceinline__ void gsync(int idx, int nb) {
    __syncthreads();
    if (threadIdx.x == 0) {
        __threadfence();                       // release
        atomicAdd(&g_ctr[idx], 1);
        while (((volatile int*)g_ctr)[idx] < nb) { }
        __threadfence();                       // acquire
    }
    __syncthreads();
}

// ============ k_graph: detect + count + wsplit + scan + dinv + fill ============
__global__ void __launch_bounds__(GT) k_graph(const void* __restrict__ ei,
                                              const float* __restrict__ W1,
                                              int n, int e, int nb) {
    __shared__ int s_is64;
    __shared__ int wsum[32];
    __shared__ int s_pre;
    int tid = threadIdx.x, lane = tid & 31, wid = tid >> 5;
    int b = blockIdx.x;
    int gstep = nb * GT;
    int gtid = b * GT + tid;

    if (tid == 0) {
        const unsigned* w = (const unsigned*)ei;
        int all0 = 1;
        for (int j = 1; j < 128; j += 2) all0 &= (w[j] == 0u);
        s_is64 = all0;
    }
    __syncthreads();
    int is64 = s_is64;

    // ---- phase0: degree count + W1 tf32 split ----
    for (int i = gtid; i < e; i += gstep) {
        int t = is64 ? (int)((const long long*)ei)[(long long)e + i]
                     : ((const int*)ei)[e + i];
        if ((unsigned)t < (unsigned)n) atomicAdd(&g_cnt[t], 1);
    }
    for (int i = gtid; i < DD * DD; i += gstep) {
        float f = W1[i];
        uint32_t h = f2tf(f);
        g_wh[i] = h;
        g_wl[i] = f2tf(f - __uint_as_float(h));
    }
    gsync(0, nb);

    // ---- phase1: per-block exclusive scan of its 1024-count segment ----
    int i = b * GT + tid;
    int v = (i < n) ? g_cnt[i] : 0;
    int incl = v;
#pragma unroll
    for (int d = 1; d < 32; d <<= 1) {
        int y = __shfl_up_sync(0xffffffffu, incl, d);
        if (lane >= d) incl += y;
    }
    if (lane == 31) wsum[wid] = incl;
    __syncthreads();
    if (wid == 0) {
        int s = wsum[lane];
#pragma unroll
        for (int d = 1; d < 32; d <<= 1) {
            int y = __shfl_up_sync(0xffffffffu, s, d);
            if (lane >= d) s += y;
        }
        wsum[lane] = s;
    }
    __syncthreads();
    int wprev = wid ? wsum[wid - 1] : 0;
    int excl = wprev + incl - v;
    if (i < n) g_off[i] = excl;
    if (tid == GT - 1) g_bsum[b] = wprev + incl;
    gsync(1, nb);

    // ---- phase2: propagate block prefix; dinv; zero g_cnt for next replay ----
    if (tid == 0) {
        int p = 0;
        for (int j = 0; j < b; j++) p += g_bsum[j];
        s_pre = p;
        if (b == nb - 1) g_off[n] = p + g_bsum[b];
    }
    __syncthreads();
    if (i < n) {
        g_off[i] += s_pre;
        g_dinv[i] = rsqrtf((float)(g_cnt[i] + 1));   // +1 = self-loop
        g_cnt[i] = 0;
    }
    gsync(2, nb);

    // ---- phase3: CSR fill ----
    for (int idx = gtid; idx < e; idx += gstep) {
        int t = is64 ? (int)((const long long*)ei)[(long long)e + idx]
                     : ((const int*)ei)[e + idx];
        int s = is64 ? (int)((const long long*)ei)[idx]
                     : ((const int*)ei)[idx];
        if ((unsigned)t < (unsigned)n && (unsigned)s < (unsigned)n) {
            int p = atomicAdd(&g_cur[t], 1);
            g_csr[g_off[t] + p] = s;
        }
    }
}

#define SX 136   // smem row stride in words (conflict-free fragment loads)

// ---------------- GEMM1: 3xtf32, double-buffered, fp16 output ----------------
__global__ void __launch_bounds__(256, 2)
k_gemm1_tc(const float* __restrict__ x, int n) {
    __shared__ uint32_t Xh[2][16 * SX], Xl[2][16 * SX];
    __shared__ uint32_t Wh[2][16 * SX], Wl[2][16 * SX];
    int tid = threadIdx.x;
    int wid = tid >> 5, lane = tid & 31;
    int gid = lane >> 2, tig = lane & 3;
    int warpM = wid & 3;
    int warpN = wid >> 2;
    int row0 = blockIdx.x * 128;

    float acc[2][8][4];
#pragma unroll
    for (int mt = 0; mt < 2; mt++)
#pragma unroll
        for (int nt = 0; nt < 8; nt++)
#pragma unroll
            for (int j = 0; j < 4; j++) acc[mt][nt][j] = 0.f;

    auto load_chunk = [&](int kc, int b) {
        int kk = kc * 16;
#pragma unroll
        for (int j = 0; j < 2; j++) {
            int idx = tid + j * 256;
            int r = idx >> 2, kq = idx & 3;
            float4 v = make_float4(0.f, 0.f, 0.f, 0.f);
            if (row0 + r < n)
                v = *(const float4*)(x + (size_t)(row0 + r) * DD + kk + kq * 4);
            float f[4] = {v.x, v.y, v.z, v.w};
#pragma unroll
            for (int i = 0; i < 4; i++) {
                uint32_t h = f2tf(f[i]);
                Xh[b][(kq * 4 + i) * SX + r] = h;
                Xl[b][(kq * 4 + i) * SX + r] = f2tf(f[i] - __uint_as_float(h));
            }
        }
#pragma unroll
        for (int j = 0; j < 2; j++) {
            int idx = tid + j * 256;
            int k = idx >> 5, c4 = idx & 31;
            *(uint4*)&Wh[b][k * SX + c4 * 4] =
                ((const uint4*)g_wh)[(size_t)(kk + k) * 32 + c4];
            *(uint4*)&Wl[b][k * SX + c4 * 4] =
                ((const uint4*)g_wl)[(size_t)(kk + k) * 32 + c4];
        }
    };

    load_chunk(0, 0);
    __syncthreads();

    for (int kc = 0; kc < 8; kc++) {
        int cur = kc & 1;
        if (kc < 7) load_chunk(kc + 1, cur ^ 1);
#pragma unroll
        for (int kb = 0; kb < 16; kb += 8) {
            uint32_t ah[2][4], al[2][4];
#pragma unroll
            for (int mt = 0; mt < 2; mt++) {
                int r = warpM * 32 + mt * 16 + gid;
                int kr0 = (kb + tig) * SX, kr4 = (kb + tig + 4) * SX;
                ah[mt][0] = Xh[cur][kr0 + r];     al[mt][0] = Xl[cur][kr0 + r];
                ah[mt][1] = Xh[cur][kr0 + r + 8]; al[mt][1] = Xl[cur][kr0 + r + 8];
                ah[mt][2] = Xh[cur][kr4 + r];     al[mt][2] = Xl[cur][kr4 + r];
                ah[mt][3] = Xh[cur][kr4 + r + 8]; al[mt][3] = Xl[cur][kr4 + r + 8];
            }
#pragma unroll
            for (int nt = 0; nt < 8; nt++) {
                int c = warpN * 64 + nt * 8 + gid;
                uint32_t bh[2], bl[2];
                bh[0] = Wh[cur][(kb + tig) * SX + c];
                bh[1] = Wh[cur][(kb + tig + 4) * SX + c];
                bl[0] = Wl[cur][(kb + tig) * SX + c];
                bl[1] = Wl[cur][(kb + tig + 4) * SX + c];
#pragma unroll
                for (int mt = 0; mt < 2; mt++) {
                    mma8(acc[mt][nt], ah[mt], bh);
                    mma8(acc[mt][nt], al[mt], bh);
                    mma8(acc[mt][nt], ah[mt], bl);
                }
            }
        }
        __syncthreads();
    }

    // epilogue: pack c0,c1 (cols 2tig,2tig+1) into one half2 word per row
#pragma unroll
    for (int mt = 0; mt < 2; mt++) {
#pragma unroll
        for (int nt = 0; nt < 8; nt++) {
            int row = row0 + warpM * 32 + mt * 16 + gid;
            int h2c = warpN * 32 + nt * 4 + tig;   // (col>>1), col=warpN*64+nt*8+2tig
            if (row < n) {
                __half2 p = __floats2half2_rn(acc[mt][nt][0], acc[mt][nt][1]);
                g_h1h[(size_t)row * 64 + h2c] = *(uint32_t*)&p;
            }
            if (row + 8 < n) {
                __half2 p = __floats2half2_rn(acc[mt][nt][2], acc[mt][nt][3]);
                g_h1h[(size_t)(row + 8) * 64 + h2c] = *(uint32_t*)&p;
            }
        }
    }
}

// unpack one 8-byte (2x half2) gather into 4 floats and fma-accumulate
__device__ __forceinline__ void acc_h4(float2 raw, float w,
                                       float& x, float& y, float& z, float& q) {
    __half2 p0 = *(__half2*)&raw.x;
    __half2 p1 = *(__half2*)&raw.y;
    float2 f0 = __half22float2(p0);
    float2 f1 = __half22float2(p1);
    x += f0.x * w; y += f0.y * w; z += f1.x * w; q += f1.y * w;
}

// ------- agg1 + bias + relu + W2 projection; also resets g_cur/g_ctr -------
__global__ void __launch_bounds__(256) k_agg1(const float* __restrict__ b1,
                                              const float* __restrict__ W2, int n) {
    int gw = (blockIdx.x * blockDim.x + threadIdx.x) >> 5;
    int lane = threadIdx.x & 31;
    if (gw >= n) return;
    if (lane == 0) {
        g_cur[gw] = 0;
        if (gw == 0) { g_ctr[0] = 0; g_ctr[1] = 0; g_ctr[2] = 0; }
    }
    float dn = g_dinv[gw];
    const float2* h = (const float2*)g_h1h;   // 32 float2 (=8B) per row
    float s = dn * dn;
    float a0x, a0y, a0z, a0w;
    {
        float2 own = h[(size_t)gw * 32 + lane];
        a0x = a0y = a0z = a0w = 0.f;
        acc_h4(own, s, a0x, a0y, a0z, a0w);
    }
    float a1x = 0.f, a1y = 0.f, a1z = 0.f, a1w = 0.f;
    int e0 = g_off[gw], e1 = g_off[gw + 1];
    int e = e0;
    for (; e + 3 < e1; e += 4) {
        int s0 = g_csr[e], s1 = g_csr[e + 1], s2 = g_csr[e + 2], s3 = g_csr[e + 3];
        float w0 = g_dinv[s0] * dn, w1 = g_dinv[s1] * dn;
        float w2 = g_dinv[s2] * dn, w3 = g_dinv[s3] * dn;
        float2 v0 = h[(size_t)s0 * 32 + lane];
        float2 v1 = h[(size_t)s1 * 32 + lane];
        float2 v2 = h[(size_t)s2 * 32 + lane];
        float2 v3 = h[(size_t)s3 * 32 + lane];
        acc_h4(v0, w0, a0x, a0y, a0z, a0w);
        acc_h4(v1, w1, a1x, a1y, a1z, a1w);
        acc_h4(v2, w2, a0x, a0y, a0z, a0w);
        acc_h4(v3, w3, a1x, a1y, a1z, a1w);
    }
    for (; e < e1; e++) {
        int s0 = g_csr[e];
        float w0 = g_dinv[s0] * dn;
        float2 v0 = h[(size_t)s0 * 32 + lane];
        acc_h4(v0, w0, a0x, a0y, a0z, a0w);
    }
    float4 b = ((const float4*)b1)[lane];
    float ax = fmaxf(a0x + a1x + b.x, 0.f);
    float ay = fmaxf(a0y + a1y + b.y, 0.f);
    float az = fmaxf(a0z + a1z + b.z, 0.f);
    float aw = fmaxf(a0w + a1w + b.w, 0.f);
    const float2* w2p = (const float2*)W2;
    float2 w0 = w2p[lane * 4 + 0], w1 = w2p[lane * 4 + 1];
    float2 w2v = w2p[lane * 4 + 2], w3 = w2p[lane * 4 + 3];
    float o0 = ax * w0.x + ay * w1.x + az * w2v.x + aw * w3.x;
    float o1 = ax * w0.y + ay * w1.y + az * w2v.y + aw * w3.y;
#pragma unroll
    for (int d = 16; d; d >>= 1) {
        o0 += __shfl_xor_sync(0xffffffffu, o0, d);
        o1 += __shfl_xor_sync(0xffffffffu, o1, d);
    }
    if (lane == 0) g_h2w[gw] = make_float2(o0, o1);
}

// ---------------- Aggregate layer 2 (thread per node, unroll 4) ----------------
__global__ void k_agg2(const float* __restrict__ b2, float* __restrict__ out, int n) {
    int i = blockIdx.x * blockDim.x + threadIdx.x;
    if (i >= n) return;
    float dn = g_dinv[i];
    float2 hv = g_h2w[i];
    float p0 = hv.x * dn * dn + b2[0];
    float p1 = hv.y * dn * dn + b2[1];
    float q0 = 0.f, q1 = 0.f;
    int e0 = g_off[i], e1 = g_off[i + 1];
    int e = e0;
    for (; e + 3 < e1; e += 4) {
        int s0 = g_csr[e], s1 = g_csr[e + 1], s2 = g_csr[e + 2], s3 = g_csr[e + 3];
        float w0 = g_dinv[s0] * dn, w1 = g_dinv[s1] * dn;
        float w2 = g_dinv[s2] * dn, w3 = g_dinv[s3] * dn;
        float2 v0 = g_h2w[s0], v1 = g_h2w[s1], v2 = g_h2w[s2], v3 = g_h2w[s3];
        p0 += v0.x * w0; p1 += v0.y * w0;
        q0 += v1.x * w1; q1 += v1.y * w1;
        p0 += v2.x * w2; p1 += v2.y * w2;
        q0 += v3.x * w3; q1 += v3.y * w3;
    }
    for (; e < e1; e++) {
        int s0 = g_csr[e];
        float w0 = g_dinv[s0] * dn;
        float2 v0 = g_h2w[s0];
        p0 += v0.x * w0; p1 += v0.y * w0;
    }
    ((float2*)out)[i] = make_float2(p0 + q0, p1 + q1);
}

// ---------------- launch ----------------
extern "C" void kernel_launch(void* const* d_in, const int* in_sizes, int n_in,
                              void* d_out, int out_size) {
    const float* x  = (const float*)d_in[0];
    const void*  ei = d_in[1];
    const float* W1 = (const float*)d_in[2];
    const float* b1 = (const float*)d_in[3];
    const float* W2 = (const float*)d_in[4];
    const float* b2 = (const float*)d_in[5];
    float* out = (float*)d_out;

    const int n = in_sizes[0] / DD;       // 100000
    const int e = in_sizes[1] / 2;        // 600000

    k_graph<<<GB, GT>>>(ei, W1, n, e, GB);
    k_gemm1_tc<<<(n + 127) / 128, 256>>>(x, n);
    k_agg1<<<(n + 7) / 8, 256>>>(b1, W2, n);
    k_agg2<<<(n + 255) / 256, 256>>>(b2, out, n);
}

// round 9
// speedup vs baseline: 1.5278x; 1.4556x over previous
#include <cuda_runtime.h>
#include <cuda_fp16.h>
#include <cstdint>

#define NN 100000
#define EE 600000
#define DD 128
#define GB 98            // k_graph grid (all blocks resident: 98 <= 148 SMs)
#define GT 1024          // k_graph block
#define SX 136           // smem row stride in words

// ---- device scratch (allocation-free rule: __device__ globals) ----
__device__ __align__(16) uint32_t g_h1h[(size_t)NN * 64]; // x @ W1, fp16x2 packed
__device__ __align__(16) float2 g_h2w[NN];               // relu(agg1+b1) @ W2
__device__ __align__(16) uint32_t g_w16[64 * DD];        // W1 packed half2 [k2][n]
__device__ int   g_cnt[NN];      // zeroed at end of each pass (phase2)
__device__ int   g_cur[NN];      // zeroed by k_agg1 each pass
__device__ int   g_off[NN + 1];
__device__ int   g_bsum[GB];
__device__ int   g_csr[EE];
__device__ float g_dinv[NN];
__device__ int   g_ctr[3];       // grid barriers; zeroed by k_agg1 each pass

// ---------------- grid barrier (all GB blocks resident) ----------------
__device__ __forceinline__ void gsync(int idx, int nb) {
    __syncthreads();
    if (threadIdx.x == 0) {
        __threadfence();
        atomicAdd(&g_ctr[idx], 1);
        while (((volatile int*)g_ctr)[idx] < nb) { }
        __threadfence();
    }
    __syncthreads();
}

// ============ k_graph: detect + count + wpack + scan + dinv + fill ============
__global__ void __launch_bounds__(GT) k_graph(const void* __restrict__ ei,
                                              const float* __restrict__ W1,
                                              int n, int e, int nb) {
    __shared__ int s_is64;
    __shared__ int wsum[32];
    __shared__ int s_pre;
    int tid = threadIdx.x, lane = tid & 31, wid = tid >> 5;
    int b = blockIdx.x;
    int gstep = nb * GT;
    int gtid = b * GT + tid;

    if (tid == 0) {
        const unsigned* w = (const unsigned*)ei;
        int all0 = 1;
        for (int j = 1; j < 128; j += 2) all0 &= (w[j] == 0u);
        s_is64 = all0;
    }
    __syncthreads();
    int is64 = s_is64;

    // ---- phase0: degree count + W1 fp16 pack [k2][n] ----
    for (int i = gtid; i < e; i += gstep) {
        int t = is64 ? (int)((const long long*)ei)[(long long)e + i]
                     : ((const int*)ei)[e + i];
        if ((unsigned)t < (unsigned)n) atomicAdd(&g_cnt[t], 1);
    }
    for (int i = gtid; i < 64 * DD; i += gstep) {
        int k2 = i >> 7, nn = i & 127;
        __half2 p = __floats2half2_rn(W1[(2 * k2) * DD + nn],
                                      W1[(2 * k2 + 1) * DD + nn]);
        g_w16[i] = *(uint32_t*)&p;
    }
    gsync(0, nb);

    // ---- phase1: per-block exclusive scan of its 1024-count segment ----
    int i = b * GT + tid;
    int v = (i < n) ? g_cnt[i] : 0;
    int incl = v;
#pragma unroll
    for (int d = 1; d < 32; d <<= 1) {
        int y = __shfl_up_sync(0xffffffffu, incl, d);
        if (lane >= d) incl += y;
    }
    if (lane == 31) wsum[wid] = incl;
    __syncthreads();
    if (wid == 0) {
        int s = wsum[lane];
#pragma unroll
        for (int d = 1; d < 32; d <<= 1) {
            int y = __shfl_up_sync(0xffffffffu, s, d);
            if (lane >= d) s += y;
        }
        wsum[lane] = s;
    }
    __syncthreads();
    int wprev = wid ? wsum[wid - 1] : 0;
    int excl = wprev + incl - v;
    if (i < n) g_off[i] = excl;
    if (tid == GT - 1) g_bsum[b] = wprev + incl;
    gsync(1, nb);

    // ---- phase2: propagate block prefix; dinv; zero g_cnt for replay ----
    if (tid == 0) {
        int p = 0;
        for (int j = 0; j < b; j++) p += g_bsum[j];
        s_pre = p;
        if (b == nb - 1) g_off[n] = p + g_bsum[b];
    }
    __syncthreads();
    if (i < n) {
        g_off[i] += s_pre;
        g_dinv[i] = rsqrtf((float)(g_cnt[i] + 1));   // +1 = self-loop
        g_cnt[i] = 0;
    }
    gsync(2, nb);

    // ---- phase3: CSR fill ----
    for (int idx = gtid; idx < e; idx += gstep) {
        int t = is64 ? (int)((const long long*)ei)[(long long)e + idx]
                     : ((const int*)ei)[e + idx];
        int s = is64 ? (int)((const long long*)ei)[idx]
                     : ((const int*)ei)[idx];
        if ((unsigned)t < (unsigned)n && (unsigned)s < (unsigned)n) {
            int p = atomicAdd(&g_cur[t], 1);
            g_csr[g_off[t] + p] = s;
        }
    }
}

// ---------------- fp16 mma ----------------
__device__ __forceinline__ void mma16(float* c, const uint32_t* a, const uint32_t* b) {
    asm volatile(
        "mma.sync.aligned.m16n8k16.row.col.f32.f16.f16.f32 "
        "{%0,%1,%2,%3},{%4,%5,%6,%7},{%8,%9},{%0,%1,%2,%3};"
        : "+f"(c[0]), "+f"(c[1]), "+f"(c[2]), "+f"(c[3])
        : "r"(a[0]), "r"(a[1]), "r"(a[2]), "r"(a[3]), "r"(b[0]), "r"(b[1]));
}

// ---------------- GEMM1: fp16 tensor cores, fp32 accum, fp16 out ----------------
// Block 128x128, 8 warps (4 over M x 2 over N), K in 2 chunks of 64.
// smem layout [k2][idx] with XOR swizzle (idx ^ ((k2>>1)&31)) — conflict-free.
__global__ void __launch_bounds__(256, 2)
k_gemm1_tc(const float* __restrict__ x, int n) {
    __shared__ uint32_t Xs[32 * SX];   // chunk: 32 k2 x 128 rows
    __shared__ uint32_t Ws[32 * SX];   // chunk: 32 k2 x 128 cols
    int tid = threadIdx.x;
    int wid = tid >> 5, lane = tid & 31;
    int gid = lane >> 2, tig = lane & 3;
    int warpM = wid & 3;
    int warpN = wid >> 2;
    int row0 = blockIdx.x * 128;

    float acc[2][8][4];
#pragma unroll
    for (int mt = 0; mt < 2; mt++)
#pragma unroll
        for (int nt = 0; nt < 8; nt++)
#pragma unroll
            for (int j = 0; j < 4; j++) acc[mt][nt][j] = 0.f;

    for (int c = 0; c < 2; c++) {
        // X chunk: 128 rows x 16 float4 (k = c*64..c*64+63)
#pragma unroll
        for (int j = 0; j < 8; j++) {
            int idx = tid + j * 256;       // 2048 float4
            int r = idx >> 4, q = idx & 15;
            float4 v = make_float4(0.f, 0.f, 0.f, 0.f);
            if (row0 + r < n)
                v = *(const float4*)(x + (size_t)(row0 + r) * DD + c * 64 + q * 4);
            __half2 p0 = __floats2half2_rn(v.x, v.y);
            __half2 p1 = __floats2half2_rn(v.z, v.w);
            int rs = r ^ q;                // swizzle: m(2q)=m(2q+1)=q
            Xs[(2 * q) * SX + rs]     = *(uint32_t*)&p0;
            Xs[(2 * q + 1) * SX + rs] = *(uint32_t*)&p1;
        }
        // W chunk: 32 k2 x 128 n from packed g_w16
#pragma unroll
        for (int j = 0; j < 16; j++) {
            int idx = tid + j * 256;       // 4096 words
            int k2 = idx >> 7, nn = idx & 127;
            uint32_t w = g_w16[(size_t)(c * 32 + k2) * DD + nn];
            Ws[k2 * SX + (nn ^ ((k2 >> 1) & 31))] = w;
        }
        __syncthreads();

#pragma unroll
        for (int ks = 0; ks < 4; ks++) {
            int m0 = ks * 4 + (tig >> 1);
            int m1 = m0 + 2;
            int k2a = ks * 8 + tig, k2b = k2a + 4;
            uint32_t a[2][4];
#pragma unroll
            for (int mt = 0; mt < 2; mt++) {
                int rb = warpM * 32 + mt * 16 + gid;
                a[mt][0] = Xs[k2a * SX + (rb ^ m0)];
                a[mt][1] = Xs[k2a * SX + ((rb + 8) ^ m0)];
                a[mt][2] = Xs[k2b * SX + (rb ^ m1)];
                a[mt][3] = Xs[k2b * SX + ((rb + 8) ^ m1)];
            }
#pragma unroll
            for (int nt = 0; nt < 8; nt++) {
                int nb = warpN * 64 + nt * 8 + gid;
                uint32_t b[2];
                b[0] = Ws[k2a * SX + (nb ^ m0)];
                b[1] = Ws[k2b * SX + (nb ^ m1)];
#pragma unroll
                for (int mt = 0; mt < 2; mt++)
                    mma16(acc[mt][nt], a[mt], b);
            }
        }
        __syncthreads();
    }

    // epilogue: pack (c0,c1) / (c2,c3) into half2 words
#pragma unroll
    for (int mt = 0; mt < 2; mt++) {
#pragma unroll
        for (int nt = 0; nt < 8; nt++) {
            int row = row0 + warpM * 32 + mt * 16 + gid;
            int h2c = warpN * 32 + nt * 4 + tig;   // col/2
            if (row < n) {
                __half2 p = __floats2half2_rn(acc[mt][nt][0], acc[mt][nt][1]);
                g_h1h[(size_t)row * 64 + h2c] = *(uint32_t*)&p;
            }
            if (row + 8 < n) {
                __half2 p = __floats2half2_rn(acc[mt][nt][2], acc[mt][nt][3]);
                g_h1h[(size_t)(row + 8) * 64 + h2c] = *(uint32_t*)&p;
            }
        }
    }
}

// unpack one 8-byte (2x half2) gather into 4 floats and fma-accumulate
__device__ __forceinline__ void acc_h4(float2 raw, float w,
                                       float& x, float& y, float& z, float& q) {
    __half2 p0 = *(__half2*)&raw.x;
    __half2 p1 = *(__half2*)&raw.y;
    float2 f0 = __half22float2(p0);
    float2 f1 = __half22float2(p1);
    x += f0.x * w; y += f0.y * w; z += f1.x * w; q += f1.y * w;
}

// ------- agg1 + bias + relu + W2 projection; also resets g_cur/g_ctr -------
__global__ void __launch_bounds__(256) k_agg1(const float* __restrict__ b1,
                                              const float* __restrict__ W2, int n) {
    int gw = (blockIdx.x * blockDim.x + threadIdx.x) >> 5;
    int lane = threadIdx.x & 31;
    if (gw >= n) return;
    if (lane == 0) {
        g_cur[gw] = 0;
        if (gw == 0) { g_ctr[0] = 0; g_ctr[1] = 0; g_ctr[2] = 0; }
    }
    float dn = g_dinv[gw];
    const float2* h = (const float2*)g_h1h;   // 32 float2 (=8B) per row
    float s = dn * dn;
    float a0x, a0y, a0z, a0w;
    {
        float2 own = h[(size_t)gw * 32 + lane];
        a0x = a0y = a0z = a0w = 0.f;
        acc_h4(own, s, a0x, a0y, a0z, a0w);
    }
    float a1x = 0.f, a1y = 0.f, a1z = 0.f, a1w = 0.f;
    int e0 = g_off[gw], e1 = g_off[gw + 1];
    int e = e0;
    for (; e + 3 < e1; e += 4) {
        int s0 = g_csr[e], s1 = g_csr[e + 1], s2 = g_csr[e + 2], s3 = g_csr[e + 3];
        float w0 = g_dinv[s0] * dn, w1 = g_dinv[s1] * dn;
        float w2 = g_dinv[s2] * dn, w3 = g_dinv[s3] * dn;
        float2 v0 = h[(size_t)s0 * 32 + lane];
        float2 v1 = h[(size_t)s1 * 32 + lane];
        float2 v2 = h[(size_t)s2 * 32 + lane];
        float2 v3 = h[(size_t)s3 * 32 + lane];
        acc_h4(v0, w0, a0x, a0y, a0z, a0w);
        acc_h4(v1, w1, a1x, a1y, a1z, a1w);
        acc_h4(v2, w2, a0x, a0y, a0z, a0w);
        acc_h4(v3, w3, a1x, a1y, a1z, a1w);
    }
    for (; e < e1; e++) {
        int s0 = g_csr[e];
        float w0 = g_dinv[s0] * dn;
        float2 v0 = h[(size_t)s0 * 32 + lane];
        acc_h4(v0, w0, a0x, a0y, a0z, a0w);
    }
    float4 b = ((const float4*)b1)[lane];
    float ax = fmaxf(a0x + a1x + b.x, 0.f);
    float ay = fmaxf(a0y + a1y + b.y, 0.f);
    float az = fmaxf(a0z + a1z + b.z, 0.f);
    float aw = fmaxf(a0w + a1w + b.w, 0.f);
    const float2* w2p = (const float2*)W2;
    float2 w0 = w2p[lane * 4 + 0], w1 = w2p[lane * 4 + 1];
    float2 w2v = w2p[lane * 4 + 2], w3 = w2p[lane * 4 + 3];
    float o0 = ax * w0.x + ay * w1.x + az * w2v.x + aw * w3.x;
    float o1 = ax * w0.y + ay * w1.y + az * w2v.y + aw * w3.y;
#pragma unroll
    for (int d = 16; d; d >>= 1) {
        o0 += __shfl_xor_sync(0xffffffffu, o0, d);
        o1 += __shfl_xor_sync(0xffffffffu, o1, d);
    }
    if (lane == 0) g_h2w[gw] = make_float2(o0, o1);
}

// ---------------- Aggregate layer 2 (thread per node, unroll 4) ----------------
__global__ void k_agg2(const float* __restrict__ b2, float* __restrict__ out, int n) {
    int i = blockIdx.x * blockDim.x + threadIdx.x;
    if (i >= n) return;
    float dn = g_dinv[i];
    float2 hv = g_h2w[i];
    float p0 = hv.x * dn * dn + b2[0];
    float p1 = hv.y * dn * dn + b2[1];
    float q0 = 0.f, q1 = 0.f;
    int e0 = g_off[i], e1 = g_off[i + 1];
    int e = e0;
    for (; e + 3 < e1; e += 4) {
        int s0 = g_csr[e], s1 = g_csr[e + 1], s2 = g_csr[e + 2], s3 = g_csr[e + 3];
        float w0 = g_dinv[s0] * dn, w1 = g_dinv[s1] * dn;
        float w2 = g_dinv[s2] * dn, w3 = g_dinv[s3] * dn;
        float2 v0 = g_h2w[s0], v1 = g_h2w[s1], v2 = g_h2w[s2], v3 = g_h2w[s3];
        p0 += v0.x * w0; p1 += v0.y * w0;
        q0 += v1.x * w1; q1 += v1.y * w1;
        p0 += v2.x * w2; p1 += v2.y * w2;
        q0 += v3.x * w3; q1 += v3.y * w3;
    }
    for (; e < e1; e++) {
        int s0 = g_csr[e];
        float w0 = g_dinv[s0] * dn;
        float2 v0 = g_h2w[s0];
        p0 += v0.x * w0; p1 += v0.y * w0;
    }
    ((float2*)out)[i] = make_float2(p0 + q0, p1 + q1);
}

// ---------------- launch ----------------
extern "C" void kernel_launch(void* const* d_in, const int* in_sizes, int n_in,
                              void* d_out, int out_size) {
    const float* x  = (const float*)d_in[0];
    const void*  ei = d_in[1];
    const float* W1 = (const float*)d_in[2];
    const float* b1 = (const float*)d_in[3];
    const float* W2 = (const float*)d_in[4];
    const float* b2 = (const float*)d_in[5];
    float* out = (float*)d_out;

    const int n = in_sizes[0] / DD;       // 100000
    const int e = in_sizes[1] / 2;        // 600000

    k_graph<<<GB, GT>>>(ei, W1, n, e, GB);
    k_gemm1_tc<<<(n + 127) / 128, 256>>>(x, n);
    k_agg1<<<(n + 7) / 8, 256>>>(b1, W2, n);
    k_agg2<<<(n + 255) / 256, 256>>>(b2, out, n);
}

// round 10
// speedup vs baseline: 1.5680x; 1.0263x over previous
#include <cuda_runtime.h>
#include <cuda_fp16.h>
#include <cstdint>

#define NN 100000
#define EE 600000
#define DD 128
#define GB 98            // k_graph grid (all blocks resident: 98 <= 148 SMs)
#define GT 1024          // k_graph block
#define SX 136           // smem row stride in words

// ---- device scratch (allocation-free rule: __device__ globals) ----
__device__ __align__(16) uint32_t g_h1h[(size_t)NN * 64]; // (x@W1)*dinv, fp16x2
__device__ __align__(16) float2 g_h2w[NN];               // layer-2 lin out * dinv
__device__ __align__(16) uint32_t g_w16[64 * DD];        // W1 packed half2 [k2][n]
__device__ int   g_cnt[NN];      // zeroed at end of each pass (phase2)
__device__ int   g_cur[NN];      // zeroed by k_agg1 each pass
__device__ int   g_off[NN + 1];
__device__ int   g_bsum[GB];
__device__ int   g_csr[EE];
__device__ float g_dinv[NN];
__device__ int   g_ctr[3];       // grid barriers; zeroed by k_agg1 each pass

// ---------------- grid barrier (all GB blocks resident) ----------------
__device__ __forceinline__ void gsync(int idx, int nb) {
    __syncthreads();
    if (threadIdx.x == 0) {
        __threadfence();
        atomicAdd(&g_ctr[idx], 1);
        while (((volatile int*)g_ctr)[idx] < nb) { }
        __threadfence();
    }
    __syncthreads();
}

// ============ k_graph: detect + count + wpack + scan + dinv + fill ============
__global__ void __launch_bounds__(GT) k_graph(const void* __restrict__ ei,
                                              const float* __restrict__ W1,
                                              int n, int e, int nb) {
    __shared__ int s_is64;
    __shared__ int wsum[32];
    __shared__ int s_pre;
    int tid = threadIdx.x, lane = tid & 31, wid = tid >> 5;
    int b = blockIdx.x;
    int gstep = nb * GT;
    int gtid = b * GT + tid;

    if (tid == 0) {
        const unsigned* w = (const unsigned*)ei;
        int all0 = 1;
        for (int j = 1; j < 128; j += 2) all0 &= (w[j] == 0u);
        s_is64 = all0;
    }
    __syncthreads();
    int is64 = s_is64;

    // ---- phase0: degree count + W1 fp16 pack [k2][n] ----
    for (int i = gtid; i < e; i += gstep) {
        int t = is64 ? (int)((const long long*)ei)[(long long)e + i]
                     : ((const int*)ei)[e + i];
        if ((unsigned)t < (unsigned)n) atomicAdd(&g_cnt[t], 1);
    }
    for (int i = gtid; i < 64 * DD; i += gstep) {
        int k2 = i >> 7, nn = i & 127;
        __half2 p = __floats2half2_rn(W1[(2 * k2) * DD + nn],
                                      W1[(2 * k2 + 1) * DD + nn]);
        g_w16[i] = *(uint32_t*)&p;
    }
    gsync(0, nb);

    // ---- phase1: per-block exclusive scan of its 1024-count segment ----
    int i = b * GT + tid;
    int v = (i < n) ? g_cnt[i] : 0;
    int incl = v;
#pragma unroll
    for (int d = 1; d < 32; d <<= 1) {
        int y = __shfl_up_sync(0xffffffffu, incl, d);
        if (lane >= d) incl += y;
    }
    if (lane == 31) wsum[wid] = incl;
    __syncthreads();
    if (wid == 0) {
        int s = wsum[lane];
#pragma unroll
        for (int d = 1; d < 32; d <<= 1) {
            int y = __shfl_up_sync(0xffffffffu, s, d);
            if (lane >= d) s += y;
        }
        wsum[lane] = s;
    }
    __syncthreads();
    int wprev = wid ? wsum[wid - 1] : 0;
    int excl = wprev + incl - v;
    if (i < n) g_off[i] = excl;
    if (tid == GT - 1) g_bsum[b] = wprev + incl;
    gsync(1, nb);

    // ---- phase2: propagate block prefix; dinv; zero g_cnt for replay ----
    if (tid == 0) {
        int p = 0;
        for (int j = 0; j < b; j++) p += g_bsum[j];
        s_pre = p;
        if (b == nb - 1) g_off[n] = p + g_bsum[b];
    }
    __syncthreads();
    if (i < n) {
        g_off[i] += s_pre;
        g_dinv[i] = rsqrtf((float)(g_cnt[i] + 1));   // +1 = self-loop
        g_cnt[i] = 0;
    }
    gsync(2, nb);

    // ---- phase3: CSR fill ----
    for (int idx = gtid; idx < e; idx += gstep) {
        int t = is64 ? (int)((const long long*)ei)[(long long)e + idx]
                     : ((const int*)ei)[e + idx];
        int s = is64 ? (int)((const long long*)ei)[idx]
                     : ((const int*)ei)[idx];
        if ((unsigned)t < (unsigned)n && (unsigned)s < (unsigned)n) {
            int p = atomicAdd(&g_cur[t], 1);
            g_csr[g_off[t] + p] = s;
        }
    }
}

// ---------------- fp16 mma ----------------
__device__ __forceinline__ void mma16(float* c, const uint32_t* a, const uint32_t* b) {
    asm volatile(
        "mma.sync.aligned.m16n8k16.row.col.f32.f16.f16.f32 "
        "{%0,%1,%2,%3},{%4,%5,%6,%7},{%8,%9},{%0,%1,%2,%3};"
        : "+f"(c[0]), "+f"(c[1]), "+f"(c[2]), "+f"(c[3])
        : "r"(a[0]), "r"(a[1]), "r"(a[2]), "r"(a[3]), "r"(b[0]), "r"(b[1]));
}

// ------- GEMM1: fp16 MMA, fp32 accum; epilogue scales row by dinv[row] -------
__global__ void __launch_bounds__(256, 2)
k_gemm1_tc(const float* __restrict__ x, int n) {
    __shared__ uint32_t Xs[32 * SX];
    __shared__ uint32_t Ws[32 * SX];
    int tid = threadIdx.x;
    int wid = tid >> 5, lane = tid & 31;
    int gid = lane >> 2, tig = lane & 3;
    int warpM = wid & 3;
    int warpN = wid >> 2;
    int row0 = blockIdx.x * 128;

    float acc[2][8][4];
#pragma unroll
    for (int mt = 0; mt < 2; mt++)
#pragma unroll
        for (int nt = 0; nt < 8; nt++)
#pragma unroll
            for (int j = 0; j < 4; j++) acc[mt][nt][j] = 0.f;

    for (int c = 0; c < 2; c++) {
#pragma unroll
        for (int j = 0; j < 8; j++) {
            int idx = tid + j * 256;
            int r = idx >> 4, q = idx & 15;
            float4 v = make_float4(0.f, 0.f, 0.f, 0.f);
            if (row0 + r < n)
                v = *(const float4*)(x + (size_t)(row0 + r) * DD + c * 64 + q * 4);
            __half2 p0 = __floats2half2_rn(v.x, v.y);
            __half2 p1 = __floats2half2_rn(v.z, v.w);
            int rs = r ^ q;
            Xs[(2 * q) * SX + rs]     = *(uint32_t*)&p0;
            Xs[(2 * q + 1) * SX + rs] = *(uint32_t*)&p1;
        }
#pragma unroll
        for (int j = 0; j < 16; j++) {
            int idx = tid + j * 256;
            int k2 = idx >> 7, nn = idx & 127;
            uint32_t w = g_w16[(size_t)(c * 32 + k2) * DD + nn];
            Ws[k2 * SX + (nn ^ ((k2 >> 1) & 31))] = w;
        }
        __syncthreads();

#pragma unroll
        for (int ks = 0; ks < 4; ks++) {
            int m0 = ks * 4 + (tig >> 1);
            int m1 = m0 + 2;
            int k2a = ks * 8 + tig, k2b = k2a + 4;
            uint32_t a[2][4];
#pragma unroll
            for (int mt = 0; mt < 2; mt++) {
                int rb = warpM * 32 + mt * 16 + gid;
                a[mt][0] = Xs[k2a * SX + (rb ^ m0)];
                a[mt][1] = Xs[k2a * SX + ((rb + 8) ^ m0)];
                a[mt][2] = Xs[k2b * SX + (rb ^ m1)];
                a[mt][3] = Xs[k2b * SX + ((rb + 8) ^ m1)];
            }
#pragma unroll
            for (int nt = 0; nt < 8; nt++) {
                int nb = warpN * 64 + nt * 8 + gid;
                uint32_t b[2];
                b[0] = Ws[k2a * SX + (nb ^ m0)];
                b[1] = Ws[k2b * SX + (nb ^ m1)];
#pragma unroll
                for (int mt = 0; mt < 2; mt++)
                    mma16(acc[mt][nt], a[mt], b);
            }
        }
        __syncthreads();
    }

    // epilogue: scale by dinv[row], pack to half2
#pragma unroll
    for (int mt = 0; mt < 2; mt++) {
        int rowA = row0 + warpM * 32 + mt * 16 + gid;
        int rowB = rowA + 8;
        float dA = (rowA < n) ? g_dinv[rowA] : 0.f;
        float dB = (rowB < n) ? g_dinv[rowB] : 0.f;
#pragma unroll
        for (int nt = 0; nt < 8; nt++) {
            int h2c = warpN * 32 + nt * 4 + tig;
            if (rowA < n) {
                __half2 p = __floats2half2_rn(acc[mt][nt][0] * dA, acc[mt][nt][1] * dA);
                g_h1h[(size_t)rowA * 64 + h2c] = *(uint32_t*)&p;
            }
            if (rowB < n) {
                __half2 p = __floats2half2_rn(acc[mt][nt][2] * dB, acc[mt][nt][3] * dB);
                g_h1h[(size_t)rowB * 64 + h2c] = *(uint32_t*)&p;
            }
        }
    }
}

// unpack one 8-byte (2x half2) gather and plain-accumulate (no weight)
__device__ __forceinline__ void add_h4(float2 raw,
                                       float& x, float& y, float& z, float& q) {
    __half2 p0 = *(__half2*)&raw.x;
    __half2 p1 = *(__half2*)&raw.y;
    float2 f0 = __half22float2(p0);
    float2 f1 = __half22float2(p1);
    x += f0.x; y += f0.y; z += f1.x; q += f1.y;
}

// ------- agg1: sum pre-scaled rows, *dn, bias, relu, W2 proj, write *dn -------
__global__ void __launch_bounds__(256) k_agg1(const float* __restrict__ b1,
                                              const float* __restrict__ W2, int n) {
    int gw = (blockIdx.x * blockDim.x + threadIdx.x) >> 5;
    int lane = threadIdx.x & 31;
    if (gw >= n) return;
    if (lane == 0) {
        g_cur[gw] = 0;
        if (gw == 0) { g_ctr[0] = 0; g_ctr[1] = 0; g_ctr[2] = 0; }
    }
    float dn = g_dinv[gw];
    const float2* h = (const float2*)g_h1h;   // 32 x 8B per row
    float a0x = 0.f, a0y = 0.f, a0z = 0.f, a0w = 0.f;
    float a1x = 0.f, a1y = 0.f, a1z = 0.f, a1w = 0.f;
    add_h4(h[(size_t)gw * 32 + lane], a0x, a0y, a0z, a0w);   // self (pre-scaled)
    int e0 = g_off[gw], e1 = g_off[gw + 1];
    int e = e0;
    for (; e + 3 < e1; e += 4) {
        int s0 = g_csr[e], s1 = g_csr[e + 1], s2 = g_csr[e + 2], s3 = g_csr[e + 3];
        float2 v0 = h[(size_t)s0 * 32 + lane];
        float2 v1 = h[(size_t)s1 * 32 + lane];
        float2 v2 = h[(size_t)s2 * 32 + lane];
        float2 v3 = h[(size_t)s3 * 32 + lane];
        add_h4(v0, a0x, a0y, a0z, a0w);
        add_h4(v1, a1x, a1y, a1z, a1w);
        add_h4(v2, a0x, a0y, a0z, a0w);
        add_h4(v3, a1x, a1y, a1z, a1w);
    }
    for (; e < e1; e++) {
        float2 v0 = h[(size_t)g_csr[e] * 32 + lane];
        add_h4(v0, a0x, a0y, a0z, a0w);
    }
    float4 b = ((const float4*)b1)[lane];
    float ax = fmaxf((a0x + a1x) * dn + b.x, 0.f);
    float ay = fmaxf((a0y + a1y) * dn + b.y, 0.f);
    float az = fmaxf((a0z + a1z) * dn + b.z, 0.f);
    float aw = fmaxf((a0w + a1w) * dn + b.w, 0.f);
    const float2* w2p = (const float2*)W2;
    float2 w0 = w2p[lane * 4 + 0], w1 = w2p[lane * 4 + 1];
    float2 w2v = w2p[lane * 4 + 2], w3 = w2p[lane * 4 + 3];
    float o0 = ax * w0.x + ay * w1.x + az * w2v.x + aw * w3.x;
    float o1 = ax * w0.y + ay * w1.y + az * w2v.y + aw * w3.y;
#pragma unroll
    for (int d = 16; d; d >>= 1) {
        o0 += __shfl_xor_sync(0xffffffffu, o0, d);
        o1 += __shfl_xor_sync(0xffffffffu, o1, d);
    }
    if (lane == 0) g_h2w[gw] = make_float2(o0 * dn, o1 * dn);  // pre-scale for L2
}

// ---------------- agg2: sum pre-scaled h2w, *dn, + b2 ----------------
__global__ void k_agg2(const float* __restrict__ b2, float* __restrict__ out, int n) {
    int i = blockIdx.x * blockDim.x + threadIdx.x;
    if (i >= n) return;
    float dn = g_dinv[i];
    float2 hv = g_h2w[i];
    float p0 = hv.x, p1 = hv.y;                 // self (pre-scaled)
    float q0 = 0.f, q1 = 0.f;
    int e0 = g_off[i], e1 = g_off[i + 1];
    int e = e0;
    for (; e + 3 < e1; e += 4) {
        int s0 = g_csr[e], s1 = g_csr[e + 1], s2 = g_csr[e + 2], s3 = g_csr[e + 3];
        float2 v0 = g_h2w[s0], v1 = g_h2w[s1], v2 = g_h2w[s2], v3 = g_h2w[s3];
        p0 += v0.x; p1 += v0.y;
        q0 += v1.x; q1 += v1.y;
        p0 += v2.x; p1 += v2.y;
        q0 += v3.x; q1 += v3.y;
    }
    for (; e < e1; e++) {
        float2 v0 = g_h2w[g_csr[e]];
        p0 += v0.x; p1 += v0.y;
    }
    ((float2*)out)[i] = make_float2((p0 + q0) * dn + b2[0], (p1 + q1) * dn + b2[1]);
}

// ---------------- launch ----------------
extern "C" void kernel_launch(void* const* d_in, const int* in_sizes, int n_in,
                              void* d_out, int out_size) {
    const float* x  = (const float*)d_in[0];
    const void*  ei = d_in[1];
    const float* W1 = (const float*)d_in[2];
    const float* b1 = (const float*)d_in[3];
    const float* W2 = (const float*)d_in[4];
    const float* b2 = (const float*)d_in[5];
    float* out = (float*)d_out;

    const int n = in_sizes[0] / DD;       // 100000
    const int e = in_sizes[1] / 2;        // 600000

    k_graph<<<GB, GT>>>(ei, W1, n, e, GB);
    k_gemm1_tc<<<(n + 127) / 128, 256>>>(x, n);
    k_agg1<<<(n + 7) / 8, 256>>>(b1, W2, n);
    k_agg2<<<(n + 255) / 256, 256>>>(b2, out, n);
}